// round 3
// baseline (speedup 1.0000x reference)
#include <cuda_runtime.h>
#include <math.h>

#define SS 512
#define NROWS 32768LL

// ------------------- device scratch (no allocs allowed) -------------------
__device__ float d_embs[32768*360];
__device__ float d_Xf[32768*1024];
__device__ float d_Xb[32768*1024];
__device__ float d_q[32768*512];
__device__ float d_k[32768*512];
__device__ float d_scores[67108864];
__device__ float d_adjens[16777216];
__device__ float d_tb[16777216];
__device__ float d_x1[8388608];
__device__ float d_denom[32768];
__device__ float d_thre[64];
__device__ float d_biasf[1024];
__device__ float d_biasb[1024];
__device__ float4 d_hx4[2*16*512];
__device__ unsigned d_barc[16];

// ------------------- small prep kernels -------------------
__global__ void prep_kernel(const float* bihf, const float* bhhf,
                            const float* bihb, const float* bhhb) {
    int i = blockIdx.x*blockDim.x + threadIdx.x;
    if (i < 1024) { d_biasf[i] = bihf[i]+bhhf[i]; d_biasb[i] = bihb[i]+bhhb[i]; }
}

__global__ void init_kernel() {
    int i = blockIdx.x*blockDim.x + threadIdx.x;
    if (i < 16) d_barc[i] = 0u;
    float4 z = make_float4(0.f,0.f,0.f,0.f);
    for (int j = i; j < 2*16*512; j += blockDim.x*gridDim.x) d_hx4[j] = z;
}

__global__ void embed_kernel(const int* __restrict__ tok, const int* __restrict__ pos,
                             const int* __restrict__ post, const float* __restrict__ emb,
                             const float* __restrict__ pose, const float* __restrict__ poste) {
    int r = blockIdx.x;
    int t = tok[r], p = pos[r], q = post[r];
    float* o = d_embs + (long long)r*360;
    for (int d = threadIdx.x; d < 360; d += blockDim.x) {
        float v;
        if (d < 300)      v = emb[(long long)t*300 + d];
        else if (d < 330) v = pose[p*30 + (d-300)];
        else              v = poste[q*30 + (d-330)];
        o[d] = v;
    }
}

// ------------------- SGEMM NT: C = alpha*A[M,K]@B[N,K]^T (+bias)(/denom)(relu)
__global__ __launch_bounds__(256) void sgemm_nt(
    const float* __restrict__ A, int lda, long long sAo, long long sAi,
    const float* __restrict__ B, int ldb, long long sBo, long long sBi,
    float* __restrict__ C, int ldc, long long sCo, long long sCi,
    int innerZ, int K, float alpha,
    const float* __restrict__ bias, const float* __restrict__ denom, int relu)
{
    int z = blockIdx.z; int zo = z / innerZ; int zi = z - zo*innerZ;
    A += zo*sAo + zi*sAi; B += zo*sBo + zi*sBi; C += zo*sCo + zi*sCi;
    __shared__ float As[8][128];
    __shared__ float Bs[8][128];
    int tid = threadIdx.x;
    int tr = tid >> 1;
    int tk = (tid & 1) * 4;
    const float* Ag = A + (long long)(blockIdx.y*128 + tr)*lda + tk;
    const float* Bg = B + (long long)(blockIdx.x*128 + tr)*ldb + tk;
    float acc[8][8];
#pragma unroll
    for (int i = 0; i < 8; i++)
#pragma unroll
        for (int j = 0; j < 8; j++) acc[i][j] = 0.f;
    int tx = (tid & 15) * 8;
    int ty = (tid >> 4) * 8;
    for (int k0 = 0; k0 < K; k0 += 8) {
        float4 a4 = *(const float4*)(Ag + k0);
        float4 b4 = *(const float4*)(Bg + k0);
        __syncthreads();
        As[tk+0][tr]=a4.x; As[tk+1][tr]=a4.y; As[tk+2][tr]=a4.z; As[tk+3][tr]=a4.w;
        Bs[tk+0][tr]=b4.x; Bs[tk+1][tr]=b4.y; Bs[tk+2][tr]=b4.z; Bs[tk+3][tr]=b4.w;
        __syncthreads();
#pragma unroll
        for (int kk = 0; kk < 8; kk++) {
            float av[8], bv[8];
            *(float4*)&av[0] = *(const float4*)&As[kk][ty];
            *(float4*)&av[4] = *(const float4*)&As[kk][ty+4];
            *(float4*)&bv[0] = *(const float4*)&Bs[kk][tx];
            *(float4*)&bv[4] = *(const float4*)&Bs[kk][tx+4];
#pragma unroll
            for (int i = 0; i < 8; i++)
#pragma unroll
                for (int j = 0; j < 8; j++)
                    acc[i][j] = fmaf(av[i], bv[j], acc[i][j]);
        }
    }
    int rowBase = blockIdx.y*128 + ty;
    int colBase = blockIdx.x*128 + tx;
#pragma unroll
    for (int i = 0; i < 8; i++) {
        int row = rowBase + i;
        float rd = denom ? (1.0f/denom[row]) : 1.0f;
        float* crow = C + (long long)row*ldc + colBase;
#pragma unroll
        for (int j = 0; j < 8; j++) {
            float v = acc[i][j] * alpha;
            if (bias) v += bias[colBase + j];
            v *= rd;
            if (relu) v = fmaxf(v, 0.f);
            crow[j] = v;
        }
    }
}

// ------------------- SGEMM NN (batched): C = A[M,K]@B[K,N] -------------------
__global__ __launch_bounds__(256) void sgemm_nn(
    const float* __restrict__ A, int lda, long long sA,
    const float* __restrict__ B, int ldb, long long sB,
    float* __restrict__ C, int ldc, long long sC, int K)
{
    int z = blockIdx.z;
    A += (long long)z*sA; B += (long long)z*sB; C += (long long)z*sC;
    __shared__ float As[8][128];
    __shared__ float Bs[8][128];
    int tid = threadIdx.x;
    int tr = tid >> 1;
    int tk = (tid & 1) * 4;
    const float* Ag = A + (long long)(blockIdx.y*128 + tr)*lda + tk;
    int bk = tid >> 5;
    int bc = (tid & 31) * 4;
    const float* Bg = B + (long long)bk*ldb + blockIdx.x*128 + bc;
    float acc[8][8];
#pragma unroll
    for (int i = 0; i < 8; i++)
#pragma unroll
        for (int j = 0; j < 8; j++) acc[i][j] = 0.f;
    int tx = (tid & 15) * 8;
    int ty = (tid >> 4) * 8;
    for (int k0 = 0; k0 < K; k0 += 8) {
        float4 a4 = *(const float4*)(Ag + k0);
        float4 b4 = *(const float4*)(Bg + (long long)k0*ldb);
        __syncthreads();
        As[tk+0][tr]=a4.x; As[tk+1][tr]=a4.y; As[tk+2][tr]=a4.z; As[tk+3][tr]=a4.w;
        *(float4*)&Bs[bk][bc] = b4;
        __syncthreads();
#pragma unroll
        for (int kk = 0; kk < 8; kk++) {
            float av[8], bv[8];
            *(float4*)&av[0] = *(const float4*)&As[kk][ty];
            *(float4*)&av[4] = *(const float4*)&As[kk][ty+4];
            *(float4*)&bv[0] = *(const float4*)&Bs[kk][tx];
            *(float4*)&bv[4] = *(const float4*)&Bs[kk][tx+4];
#pragma unroll
            for (int i = 0; i < 8; i++)
#pragma unroll
                for (int j = 0; j < 8; j++)
                    acc[i][j] = fmaf(av[i], bv[j], acc[i][j]);
        }
    }
    int rowBase = blockIdx.y*128 + ty;
    int colBase = blockIdx.x*128 + tx;
#pragma unroll
    for (int i = 0; i < 8; i++) {
        float* crow = C + (long long)(rowBase+i)*ldc + colBase;
#pragma unroll
        for (int j = 0; j < 8; j++) crow[j] = acc[i][j];
    }
}

// ------------------- BiLSTM recurrence -------------------
// 128 blocks = 16 groups(8 samples x dir) x 8 j-split. Whh slice in smem.
// h exchanged via double-buffered d_hx4 + per-group software barrier.
__global__ __launch_bounds__(512) void lstm_kernel(
    const float* __restrict__ Whhf, const float* __restrict__ Whhb,
    const int* __restrict__ l, float* __restrict__ gout)
{
    extern __shared__ float sm[];
    float* Ws = sm;                 // 32768 floats (f4 layout [k4][128 rows])
    float* hs = sm + 32768;         // [8][256]
    float* gs = hs + 2048;          // [8][128]
    float* cs = gs + 1024;          // [8][32]
    int bid = blockIdx.x; int group = bid >> 3; int q = bid & 7;
    int dir = group >> 3; int sg = group & 7;
    int tid = threadIdx.x;
    const float* Whh = dir ? Whhb : Whhf;
    const float* Xd = dir ? d_Xb : d_Xf;
    for (int idx = tid; idx < 32768; idx += 512) {
        int rr = idx >> 8; int kk = idx & 255;
        int gr = ((rr>>5)<<8) + (q<<5) + (rr&31);
        Ws[(((kk>>2)*128)+rr)*4 + (kk&3)] = Whh[gr*256 + kk];
    }
    if (tid < 256) cs[tid] = 0.f;
    int ln[8]; int lmax = 0;
#pragma unroll
    for (int n = 0; n < 8; n++) { ln[n] = l[sg*8+n]; lmax = max(lmax, ln[n]); }
    int slot = tid >> 7; int r = tid & 127;
    int n0 = slot, n1 = slot + 4;
    int b0 = sg*8+n0, b1 = sg*8+n1;
    int grow = ((r>>5)<<8) + (q<<5) + (r&31);
    __syncthreads();
    const float4* Ws4 = (const float4*)Ws;
    for (int t = 0; t < lmax; t++) {
        ((float4*)hs)[tid] = __ldcg(&d_hx4[(t&1)*8192 + group*512 + tid]);
        __syncthreads();
        int t0 = dir ? (ln[n0]-1-t) : t;
        int t1 = dir ? (ln[n1]-1-t) : t;
        float acc0 = (t < ln[n0]) ? Xd[((long long)(b0*SS+t0)<<10) + grow] : 0.f;
        float acc1 = (t < ln[n1]) ? Xd[((long long)(b1*SS+t1)<<10) + grow] : 0.f;
        const float4* ha = (const float4*)(hs + n0*256);
        const float4* hb = (const float4*)(hs + n1*256);
#pragma unroll 8
        for (int k4 = 0; k4 < 64; k4++) {
            float4 w = Ws4[k4*128 + r];
            float4 x = ha[k4], y = hb[k4];
            acc0 = fmaf(w.x,x.x, fmaf(w.y,x.y, fmaf(w.z,x.z, fmaf(w.w,x.w, acc0))));
            acc1 = fmaf(w.x,y.x, fmaf(w.y,y.y, fmaf(w.z,y.z, fmaf(w.w,y.w, acc1))));
        }
        gs[n0*128 + r] = acc0; gs[n1*128 + r] = acc1;
        __syncthreads();
        if (tid < 256) {
            int n = tid >> 5, jl = tid & 31;
            if (t < ln[n]) {
                float gi = gs[n*128+jl], gf = gs[n*128+32+jl];
                float gg = gs[n*128+64+jl], go_ = gs[n*128+96+jl];
                float c = cs[n*32+jl];
                c = (1.f/(1.f+expf(-gf)))*c + (1.f/(1.f+expf(-gi)))*tanhf(gg);
                float h = (1.f/(1.f+expf(-go_)))*tanhf(c);
                cs[n*32+jl] = c;
                float* dst = (float*)&d_hx4[((t+1)&1)*8192 + group*512];
                __stcg(dst + n*256 + q*32 + jl, h);
                int bsm = sg*8+n;
                int tpos = dir ? (ln[n]-1-t) : t;
                gout[((long long)(bsm*SS+tpos))*512 + dir*256 + q*32 + jl] = h;
            }
        }
        __threadfence();
        __syncthreads();
        if (tid == 0) {
            atomicAdd(&d_barc[group], 1u);
            unsigned tgt = (unsigned)(t+1)*8u;
            while (atomicAdd(&d_barc[group], 0u) < tgt) { }
        }
        __syncthreads();
    }
}

// ------------------- masked softmax + head mean + diag -------------------
__global__ void softmax_kernel(const int* __restrict__ l, float* __restrict__ ag) {
    int row = blockIdx.x; int b = row >> 9; int i = row & 511;
    int lb = l[b];
    float* out = ag + (long long)row*512;
    int tid = threadIdx.x;
    if (i >= lb) { out[tid] = 0.f; out[tid+256] = 0.f; return; }
    __shared__ float red[8];
    float a0 = 0.f, a1 = 0.f;
    int lane = tid & 31, wid = tid >> 5;
    for (int h = 0; h < 4; h++) {
        const float* sr = d_scores + ((long long)((b*4+h)*512 + i))*512;
        float v0 = (tid < lb)     ? sr[tid]     : -3.0e38f;
        float v1 = (tid+256 < lb) ? sr[tid+256] : -3.0e38f;
        float m = fmaxf(v0, v1);
        for (int o = 16; o; o >>= 1) m = fmaxf(m, __shfl_xor_sync(0xffffffffu, m, o));
        if (lane == 0) red[wid] = m;
        __syncthreads();
        m = red[0];
#pragma unroll
        for (int w = 1; w < 8; w++) m = fmaxf(m, red[w]);
        __syncthreads();
        float e0 = (tid < lb)     ? expf(v0 - m) : 0.f;
        float e1 = (tid+256 < lb) ? expf(v1 - m) : 0.f;
        float s = e0 + e1;
        for (int o = 16; o; o >>= 1) s += __shfl_xor_sync(0xffffffffu, s, o);
        if (lane == 0) red[wid] = s;
        __syncthreads();
        s = 0.f;
#pragma unroll
        for (int w = 0; w < 8; w++) s += red[w];
        float inv = 1.f/s;
        a0 += e0*inv; a1 += e1*inv;
        __syncthreads();
    }
    a0 *= 0.25f; a1 *= 0.25f;
    if (tid == i) a0 = 1.f;
    if (tid+256 == i) a1 = 1.f;
    out[tid] = a0; out[tid+256] = a1;
}

// ------------------- exact kk-th smallest nonzero via 4-pass radix select ----
__global__ __launch_bounds__(1024) void kth_kernel(const float* __restrict__ ag) {
    __shared__ unsigned wh[32][256];
    __shared__ unsigned chist[256];
    __shared__ int s_k, s_rem; __shared__ unsigned s_pref;
    int b = blockIdx.x; int tid = threadIdx.x; int wid = tid >> 5;
    const float* f = ag + (long long)b*262144;
    for (int pass = 0; pass < 4; pass++) {
        int shift = 24 - 8*pass;
        for (int j = tid; j < 32*256; j += 1024) ((unsigned*)wh)[j] = 0u;
        __syncthreads();
        unsigned pref = (pass == 0) ? 0u : s_pref;
        int cb = -1; unsigned cc = 0;
        const float* p = f + tid*256;
        for (int j = 0; j < 256; j++) {
            unsigned ub = __float_as_uint(p[j]);
            int bin = -1;
            if (ub != 0u) {
                if (pass == 0 || (ub >> (shift+8)) == (pref >> (shift+8)))
                    bin = (int)((ub >> shift) & 255u);
            }
            if (bin == cb) cc++;
            else { if (cb >= 0) atomicAdd(&wh[wid][cb], cc); cb = bin; cc = 1u; }
        }
        if (cb >= 0) atomicAdd(&wh[wid][cb], cc);
        __syncthreads();
        if (tid < 256) {
            unsigned s = 0;
#pragma unroll
            for (int w = 0; w < 32; w++) s += wh[w][tid];
            chist[tid] = s;
        }
        __syncthreads();
        if (tid == 0) {
            if (pass == 0) {
                unsigned nnz = 0;
                for (int c = 0; c < 256; c++) nnz += chist[c];
                int kk = (int)floorf((float)((int)nnz - 512) * 0.3f);
                s_k = kk; s_rem = kk; s_pref = 0u;
            }
            if (s_k > 0) {
                int rem = s_rem; unsigned pf = s_pref;
                for (int c = 0; c < 256; c++) {
                    if ((int)chist[c] >= rem) { pf |= ((unsigned)c) << shift; break; }
                    rem -= (int)chist[c];
                }
                s_rem = rem; s_pref = pf;
            }
        }
        __syncthreads();
        if (s_k <= 0) break;
    }
    if (tid == 0) d_thre[b] = (s_k > 0) ? __uint_as_float(s_pref) : 0.f;
}

// ------------------- prune + ensemble + denom -------------------
__global__ void prune_kernel(const float* __restrict__ adj, float* __restrict__ ag) {
    int row = blockIdx.x; int b = row >> 9; int tid = threadIdx.x;
    float thre = d_thre[b];
    long long base = (long long)row*512;
    float s = 0.f;
#pragma unroll
    for (int u = 0; u < 2; u++) {
        int j = tid + u*256;
        float v = ag[base + j];
        v = (v <= thre) ? 0.f : v;
        ag[base + j] = v;
        float e = 0.5f*adj[base + j] + 0.5f*v;
        d_adjens[base + j] = e;
        s += e;
    }
    for (int o = 16; o; o >>= 1) s += __shfl_xor_sync(0xffffffffu, s, o);
    __shared__ float red[8];
    if ((tid & 31) == 0) red[tid >> 5] = s;
    __syncthreads();
    if (tid == 0) {
        float tot = 0.f;
#pragma unroll
        for (int w = 0; w < 8; w++) tot += red[w];
        d_denom[row] = tot + 1.f;
    }
}

// ------------------- host launcher -------------------
extern "C" void kernel_launch(void* const* d_in, const int* in_sizes, int n_in,
                              void* d_out, int out_size) {
    const float* adj    = (const float*)d_in[0];
    const int*   tok    = (const int*)d_in[1];
    const int*   pos    = (const int*)d_in[2];
    const int*   post   = (const int*)d_in[3];
    const int*   l      = (const int*)d_in[4];
    const float* emb    = (const float*)d_in[5];
    const float* pose   = (const float*)d_in[6];
    const float* poste  = (const float*)d_in[7];
    const float* Wih_f  = (const float*)d_in[8];
    const float* Whh_f  = (const float*)d_in[9];
    const float* bih_f  = (const float*)d_in[10];
    const float* bhh_f  = (const float*)d_in[11];
    const float* Wih_b  = (const float*)d_in[12];
    const float* Whh_b  = (const float*)d_in[13];
    const float* bih_b  = (const float*)d_in[14];
    const float* bhh_b  = (const float*)d_in[15];
    const float* Wq     = (const float*)d_in[16];
    const float* bq     = (const float*)d_in[17];
    const float* Wk     = (const float*)d_in[18];
    const float* bk     = (const float*)d_in[19];
    const float* W0     = (const float*)d_in[20];
    const float* b0     = (const float*)d_in[21];
    const float* W1     = (const float*)d_in[22];
    const float* b1     = (const float*)d_in[23];

    float* xo = (float*)d_out;                      // [B,S,256]
    float* ag = xo + 8388608;                       // [B,S,S]
    float* go = xo + 25165824;                      // [B,S,512]

    void *pv;
    cudaGetSymbolAddress(&pv, d_embs);   float* embs   = (float*)pv;
    cudaGetSymbolAddress(&pv, d_Xf);     float* Xf     = (float*)pv;
    cudaGetSymbolAddress(&pv, d_Xb);     float* Xb     = (float*)pv;
    cudaGetSymbolAddress(&pv, d_q);      float* qb     = (float*)pv;
    cudaGetSymbolAddress(&pv, d_k);      float* kb     = (float*)pv;
    cudaGetSymbolAddress(&pv, d_scores); float* sc     = (float*)pv;
    cudaGetSymbolAddress(&pv, d_adjens); float* ens    = (float*)pv;
    cudaGetSymbolAddress(&pv, d_tb);     float* tbuf   = (float*)pv;
    cudaGetSymbolAddress(&pv, d_x1);     float* x1     = (float*)pv;
    cudaGetSymbolAddress(&pv, d_denom);  float* den    = (float*)pv;
    cudaGetSymbolAddress(&pv, d_biasf);  float* biasf  = (float*)pv;
    cudaGetSymbolAddress(&pv, d_biasb);  float* biasb  = (float*)pv;

    cudaMemsetAsync(go, 0, (size_t)NROWS*512*sizeof(float));
    prep_kernel<<<4,256>>>(bih_f, bhh_f, bih_b, bhh_b);
    init_kernel<<<16,1024>>>();
    embed_kernel<<<32768,128>>>(tok, pos, post, emb, pose, poste);

    // X = embs @ Wih^T + bias   [32768,1024]
    sgemm_nt<<<dim3(8,256,1),256>>>(embs,360,0,0, Wih_f,360,0,0, Xf,1024,0,0,
                                    1,360,1.f, biasf, nullptr, 0);
    sgemm_nt<<<dim3(8,256,1),256>>>(embs,360,0,0, Wih_b,360,0,0, Xb,1024,0,0,
                                    1,360,1.f, biasb, nullptr, 0);

    cudaFuncSetAttribute(lstm_kernel, cudaFuncAttributeMaxDynamicSharedMemorySize, 36096*4);
    lstm_kernel<<<128,512,36096*4>>>(Whh_f, Whh_b, l, go);

    // q, k
    sgemm_nt<<<dim3(4,256,1),256>>>(go,512,0,0, Wq,512,0,0, qb,512,0,0,
                                    1,512,1.f, bq, nullptr, 0);
    sgemm_nt<<<dim3(4,256,1),256>>>(go,512,0,0, Wk,512,0,0, kb,512,0,0,
                                    1,512,1.f, bk, nullptr, 0);
    // scores[b,h] = q_bh @ k_bh^T / sqrt(128)
    float alpha = 1.f/sqrtf(128.f);
    sgemm_nt<<<dim3(4,4,256),256>>>(qb,512, 262144,128, kb,512, 262144,128,
                                    sc,512, 1048576,262144, 4,128, alpha,
                                    nullptr, nullptr, 0);
    softmax_kernel<<<32768,256>>>(l, ag);
    kth_kernel<<<64,1024>>>(ag);
    prune_kernel<<<32768,256>>>(adj, ag);

    // GCN layer 1: t = adjens @ g ; x1 = relu((t@W0^T+b0)/denom)
    sgemm_nn<<<dim3(4,4,64),256>>>(ens,512,262144, go,512,262144, tbuf,512,262144, 512);
    sgemm_nt<<<dim3(2,256,1),256>>>(tbuf,512,0,0, W0,512,0,0, x1,256,0,0,
                                    1,512,1.f, b0, den, 1);
    // GCN layer 2: t2 = adjens @ x1 ; x = relu((t2@W1^T+b1)/denom)
    sgemm_nn<<<dim3(2,4,64),256>>>(ens,512,262144, x1,256,131072, tbuf,256,131072, 512);
    sgemm_nt<<<dim3(2,256,1),256>>>(tbuf,256,0,0, W1,256,0,0, xo,256,0,0,
                                    1,256,1.f, b1, den, 1);
    (void)in_sizes; (void)n_in; (void)out_size;
}

// round 4
// speedup vs baseline: 1.0587x; 1.0587x over previous
#include <cuda_runtime.h>
#include <math.h>

#define SS 512
#define NROWS 32768LL

// ------------------- device scratch (no allocs allowed) -------------------
__device__ float d_embs[32768*360];
__device__ float d_Xf[32768*1024];
__device__ float d_Xb[32768*1024];
__device__ float d_q[32768*512];
__device__ float d_k[32768*512];
__device__ float d_scores[67108864];
__device__ float d_adjens[16777216];
__device__ float d_tb[16777216];
__device__ float d_x1[8388608];
__device__ float d_denom[32768];
__device__ float d_thre[64];
__device__ float d_biasf[1024];
__device__ float d_biasb[1024];
__device__ float4 d_hx4[2*16*512];
__device__ unsigned d_barc[16];

// ------------------- small prep kernels -------------------
__global__ void prep_kernel(const float* bihf, const float* bhhf,
                            const float* bihb, const float* bhhb) {
    int i = blockIdx.x*blockDim.x + threadIdx.x;
    if (i < 1024) { d_biasf[i] = bihf[i]+bhhf[i]; d_biasb[i] = bihb[i]+bhhb[i]; }
}

__global__ void init_kernel() {
    int i = blockIdx.x*blockDim.x + threadIdx.x;
    if (i < 16) d_barc[i] = 0u;
    float4 z = make_float4(0.f,0.f,0.f,0.f);
    for (int j = i; j < 2*16*512; j += blockDim.x*gridDim.x) d_hx4[j] = z;
}

__global__ void embed_kernel(const int* __restrict__ tok, const int* __restrict__ pos,
                             const int* __restrict__ post, const float* __restrict__ emb,
                             const float* __restrict__ pose, const float* __restrict__ poste) {
    int r = blockIdx.x;
    int t = tok[r], p = pos[r], q = post[r];
    float* o = d_embs + (long long)r*360;
    for (int d = threadIdx.x; d < 360; d += blockDim.x) {
        float v;
        if (d < 300)      v = emb[(long long)t*300 + d];
        else if (d < 330) v = pose[p*30 + (d-300)];
        else              v = poste[q*30 + (d-330)];
        o[d] = v;
    }
}

// ------------------- SGEMM NT (double-buffered):
// C = alpha*A[M,K]@B[N,K]^T (+bias)(/denom)(relu), with optional length-skip.
// lens!=0: sample = (innerZ>1)? zo : (globalRow>>9); skip row tiles beyond l,
// and col tiles beyond l when colskip (scores case).
__global__ __launch_bounds__(256,2) void sgemm_nt(
    const float* __restrict__ A, int lda, long long sAo, long long sAi,
    const float* __restrict__ B, int ldb, long long sBo, long long sBi,
    float* __restrict__ C, int ldc, long long sCo, long long sCi,
    int innerZ, int K, float alpha,
    const float* __restrict__ bias, const float* __restrict__ denom, int relu,
    const int* __restrict__ lens, int colskip)
{
    int z = blockIdx.z; int zo = z / innerZ; int zi = z - zo*innerZ;
    if (lens) {
        int rowg = blockIdx.y*128;
        int bsm = (innerZ > 1) ? zo : (rowg >> 9);
        int lb = lens[bsm];
        int rloc = (innerZ > 1) ? rowg : (rowg & 511);
        if (rloc >= lb) return;
        if (colskip && blockIdx.x*128 >= lb) return;
    }
    A += zo*sAo + zi*sAi; B += zo*sBo + zi*sBi; C += zo*sCo + zi*sCi;
    __shared__ float As[2][8][128];
    __shared__ float Bs[2][8][128];
    int tid = threadIdx.x;
    int tr = tid >> 1;
    int tk = (tid & 1) * 4;
    const float* Ag = A + (long long)(blockIdx.y*128 + tr)*lda + tk;
    const float* Bg = B + (long long)(blockIdx.x*128 + tr)*ldb + tk;
    float acc[8][8];
#pragma unroll
    for (int i = 0; i < 8; i++)
#pragma unroll
        for (int j = 0; j < 8; j++) acc[i][j] = 0.f;
    int tx = (tid & 15) * 8;
    int ty = (tid >> 4) * 8;

    float4 a4 = *(const float4*)(Ag);
    float4 b4 = *(const float4*)(Bg);
    As[0][tk+0][tr]=a4.x; As[0][tk+1][tr]=a4.y; As[0][tk+2][tr]=a4.z; As[0][tk+3][tr]=a4.w;
    Bs[0][tk+0][tr]=b4.x; Bs[0][tk+1][tr]=b4.y; Bs[0][tk+2][tr]=b4.z; Bs[0][tk+3][tr]=b4.w;
    __syncthreads();
    int cur = 0;
    for (int k0 = 8; k0 < K; k0 += 8) {
        a4 = *(const float4*)(Ag + k0);
        b4 = *(const float4*)(Bg + k0);
#pragma unroll
        for (int kk = 0; kk < 8; kk++) {
            float av[8], bv[8];
            *(float4*)&av[0] = *(const float4*)&As[cur][kk][ty];
            *(float4*)&av[4] = *(const float4*)&As[cur][kk][ty+4];
            *(float4*)&bv[0] = *(const float4*)&Bs[cur][kk][tx];
            *(float4*)&bv[4] = *(const float4*)&Bs[cur][kk][tx+4];
#pragma unroll
            for (int i = 0; i < 8; i++)
#pragma unroll
                for (int j = 0; j < 8; j++)
                    acc[i][j] = fmaf(av[i], bv[j], acc[i][j]);
        }
        int nxt = cur ^ 1;
        As[nxt][tk+0][tr]=a4.x; As[nxt][tk+1][tr]=a4.y; As[nxt][tk+2][tr]=a4.z; As[nxt][tk+3][tr]=a4.w;
        Bs[nxt][tk+0][tr]=b4.x; Bs[nxt][tk+1][tr]=b4.y; Bs[nxt][tk+2][tr]=b4.z; Bs[nxt][tk+3][tr]=b4.w;
        __syncthreads();
        cur = nxt;
    }
#pragma unroll
    for (int kk = 0; kk < 8; kk++) {
        float av[8], bv[8];
        *(float4*)&av[0] = *(const float4*)&As[cur][kk][ty];
        *(float4*)&av[4] = *(const float4*)&As[cur][kk][ty+4];
        *(float4*)&bv[0] = *(const float4*)&Bs[cur][kk][tx];
        *(float4*)&bv[4] = *(const float4*)&Bs[cur][kk][tx+4];
#pragma unroll
        for (int i = 0; i < 8; i++)
#pragma unroll
            for (int j = 0; j < 8; j++)
                acc[i][j] = fmaf(av[i], bv[j], acc[i][j]);
    }

    int rowBase = blockIdx.y*128 + ty;
    int colBase = blockIdx.x*128 + tx;
#pragma unroll
    for (int i = 0; i < 8; i++) {
        int row = rowBase + i;
        float rd = denom ? (1.0f/denom[row]) : 1.0f;
        float* crow = C + (long long)row*ldc + colBase;
#pragma unroll
        for (int j = 0; j < 8; j++) {
            float v = acc[i][j] * alpha;
            if (bias) v += bias[colBase + j];
            v *= rd;
            if (relu) v = fmaxf(v, 0.f);
            crow[j] = v;
        }
    }
}

// ------------------- SGEMM NN (batched, double-buffered): C = A[M,K]@B[K,N] ---
__global__ __launch_bounds__(256,2) void sgemm_nn(
    const float* __restrict__ A, int lda, long long sA,
    const float* __restrict__ B, int ldb, long long sB,
    float* __restrict__ C, int ldc, long long sC, int K)
{
    int z = blockIdx.z;
    A += (long long)z*sA; B += (long long)z*sB; C += (long long)z*sC;
    __shared__ float As[2][8][128];
    __shared__ float Bs[2][8][128];
    int tid = threadIdx.x;
    int tr = tid >> 1;
    int tk = (tid & 1) * 4;
    const float* Ag = A + (long long)(blockIdx.y*128 + tr)*lda + tk;
    int bk = tid >> 5;
    int bc = (tid & 31) * 4;
    const float* Bg = B + (long long)bk*ldb + blockIdx.x*128 + bc;
    float acc[8][8];
#pragma unroll
    for (int i = 0; i < 8; i++)
#pragma unroll
        for (int j = 0; j < 8; j++) acc[i][j] = 0.f;
    int tx = (tid & 15) * 8;
    int ty = (tid >> 4) * 8;

    float4 a4 = *(const float4*)(Ag);
    float4 b4 = *(const float4*)(Bg);
    As[0][tk+0][tr]=a4.x; As[0][tk+1][tr]=a4.y; As[0][tk+2][tr]=a4.z; As[0][tk+3][tr]=a4.w;
    *(float4*)&Bs[0][bk][bc] = b4;
    __syncthreads();
    int cur = 0;
    for (int k0 = 8; k0 < K; k0 += 8) {
        a4 = *(const float4*)(Ag + k0);
        b4 = *(const float4*)(Bg + (long long)k0*ldb);
#pragma unroll
        for (int kk = 0; kk < 8; kk++) {
            float av[8], bv[8];
            *(float4*)&av[0] = *(const float4*)&As[cur][kk][ty];
            *(float4*)&av[4] = *(const float4*)&As[cur][kk][ty+4];
            *(float4*)&bv[0] = *(const float4*)&Bs[cur][kk][tx];
            *(float4*)&bv[4] = *(const float4*)&Bs[cur][kk][tx+4];
#pragma unroll
            for (int i = 0; i < 8; i++)
#pragma unroll
                for (int j = 0; j < 8; j++)
                    acc[i][j] = fmaf(av[i], bv[j], acc[i][j]);
        }
        int nxt = cur ^ 1;
        As[nxt][tk+0][tr]=a4.x; As[nxt][tk+1][tr]=a4.y; As[nxt][tk+2][tr]=a4.z; As[nxt][tk+3][tr]=a4.w;
        *(float4*)&Bs[nxt][bk][bc] = b4;
        __syncthreads();
        cur = nxt;
    }
#pragma unroll
    for (int kk = 0; kk < 8; kk++) {
        float av[8], bv[8];
        *(float4*)&av[0] = *(const float4*)&As[cur][kk][ty];
        *(float4*)&av[4] = *(const float4*)&As[cur][kk][ty+4];
        *(float4*)&bv[0] = *(const float4*)&Bs[cur][kk][tx];
        *(float4*)&bv[4] = *(const float4*)&Bs[cur][kk][tx+4];
#pragma unroll
        for (int i = 0; i < 8; i++)
#pragma unroll
            for (int j = 0; j < 8; j++)
                acc[i][j] = fmaf(av[i], bv[j], acc[i][j]);
    }
    int rowBase = blockIdx.y*128 + ty;
    int colBase = blockIdx.x*128 + tx;
#pragma unroll
    for (int i = 0; i < 8; i++) {
        float* crow = C + (long long)(rowBase+i)*ldc + colBase;
#pragma unroll
        for (int j = 0; j < 8; j++) crow[j] = acc[i][j];
    }
}

// ------------------- BiLSTM recurrence (unchanged from passing R2) -----------
__global__ __launch_bounds__(512) void lstm_kernel(
    const float* __restrict__ Whhf, const float* __restrict__ Whhb,
    const int* __restrict__ l, float* __restrict__ gout)
{
    extern __shared__ float sm[];
    float* Ws = sm;                 // 32768 floats (f4 layout [k4][128 rows])
    float* hs = sm + 32768;         // [8][256]
    float* gs = hs + 2048;          // [8][128]
    float* cs = gs + 1024;          // [8][32]
    int bid = blockIdx.x; int group = bid >> 3; int q = bid & 7;
    int dir = group >> 3; int sg = group & 7;
    int tid = threadIdx.x;
    const float* Whh = dir ? Whhb : Whhf;
    const float* Xd = dir ? d_Xb : d_Xf;
    for (int idx = tid; idx < 32768; idx += 512) {
        int rr = idx >> 8; int kk = idx & 255;
        int gr = ((rr>>5)<<8) + (q<<5) + (rr&31);
        Ws[(((kk>>2)*128)+rr)*4 + (kk&3)] = Whh[gr*256 + kk];
    }
    if (tid < 256) cs[tid] = 0.f;
    int ln[8]; int lmax = 0;
#pragma unroll
    for (int n = 0; n < 8; n++) { ln[n] = l[sg*8+n]; lmax = max(lmax, ln[n]); }
    int slot = tid >> 7; int r = tid & 127;
    int n0 = slot, n1 = slot + 4;
    int b0 = sg*8+n0, b1 = sg*8+n1;
    int grow = ((r>>5)<<8) + (q<<5) + (r&31);
    __syncthreads();
    const float4* Ws4 = (const float4*)Ws;
    for (int t = 0; t < lmax; t++) {
        ((float4*)hs)[tid] = __ldcg(&d_hx4[(t&1)*8192 + group*512 + tid]);
        __syncthreads();
        int t0 = dir ? (ln[n0]-1-t) : t;
        int t1 = dir ? (ln[n1]-1-t) : t;
        float acc0 = (t < ln[n0]) ? Xd[((long long)(b0*SS+t0)<<10) + grow] : 0.f;
        float acc1 = (t < ln[n1]) ? Xd[((long long)(b1*SS+t1)<<10) + grow] : 0.f;
        const float4* ha = (const float4*)(hs + n0*256);
        const float4* hb = (const float4*)(hs + n1*256);
#pragma unroll 8
        for (int k4 = 0; k4 < 64; k4++) {
            float4 w = Ws4[k4*128 + r];
            float4 x = ha[k4], y = hb[k4];
            acc0 = fmaf(w.x,x.x, fmaf(w.y,x.y, fmaf(w.z,x.z, fmaf(w.w,x.w, acc0))));
            acc1 = fmaf(w.x,y.x, fmaf(w.y,y.y, fmaf(w.z,y.z, fmaf(w.w,y.w, acc1))));
        }
        gs[n0*128 + r] = acc0; gs[n1*128 + r] = acc1;
        __syncthreads();
        if (tid < 256) {
            int n = tid >> 5, jl = tid & 31;
            if (t < ln[n]) {
                float gi = gs[n*128+jl], gf = gs[n*128+32+jl];
                float gg = gs[n*128+64+jl], go_ = gs[n*128+96+jl];
                float c = cs[n*32+jl];
                c = (1.f/(1.f+expf(-gf)))*c + (1.f/(1.f+expf(-gi)))*tanhf(gg);
                float h = (1.f/(1.f+expf(-go_)))*tanhf(c);
                cs[n*32+jl] = c;
                float* dst = (float*)&d_hx4[((t+1)&1)*8192 + group*512];
                __stcg(dst + n*256 + q*32 + jl, h);
                int bsm = sg*8+n;
                int tpos = dir ? (ln[n]-1-t) : t;
                gout[((long long)(bsm*SS+tpos))*512 + dir*256 + q*32 + jl] = h;
            }
        }
        __threadfence();
        __syncthreads();
        if (tid == 0) {
            atomicAdd(&d_barc[group], 1u);
            unsigned tgt = (unsigned)(t+1)*8u;
            while (atomicAdd(&d_barc[group], 0u) < tgt) { }
        }
        __syncthreads();
    }
}

// ------------------- masked softmax + head mean + diag -------------------
__global__ void softmax_kernel(const int* __restrict__ l, float* __restrict__ ag) {
    int row = blockIdx.x; int b = row >> 9; int i = row & 511;
    int lb = l[b];
    float* out = ag + (long long)row*512;
    int tid = threadIdx.x;
    if (i >= lb) { out[tid] = 0.f; out[tid+256] = 0.f; return; }
    __shared__ float red[8];
    float a0 = 0.f, a1 = 0.f;
    int lane = tid & 31, wid = tid >> 5;
    for (int h = 0; h < 4; h++) {
        const float* sr = d_scores + ((long long)((b*4+h)*512 + i))*512;
        float v0 = (tid < lb)     ? sr[tid]     : -3.0e38f;
        float v1 = (tid+256 < lb) ? sr[tid+256] : -3.0e38f;
        float m = fmaxf(v0, v1);
        for (int o = 16; o; o >>= 1) m = fmaxf(m, __shfl_xor_sync(0xffffffffu, m, o));
        if (lane == 0) red[wid] = m;
        __syncthreads();
        m = red[0];
#pragma unroll
        for (int w = 1; w < 8; w++) m = fmaxf(m, red[w]);
        __syncthreads();
        float e0 = (tid < lb)     ? expf(v0 - m) : 0.f;
        float e1 = (tid+256 < lb) ? expf(v1 - m) : 0.f;
        float s = e0 + e1;
        for (int o = 16; o; o >>= 1) s += __shfl_xor_sync(0xffffffffu, s, o);
        if (lane == 0) red[wid] = s;
        __syncthreads();
        s = 0.f;
#pragma unroll
        for (int w = 0; w < 8; w++) s += red[w];
        float inv = 1.f/s;
        a0 += e0*inv; a1 += e1*inv;
        __syncthreads();
    }
    a0 *= 0.25f; a1 *= 0.25f;
    if (tid == i) a0 = 1.f;
    if (tid+256 == i) a1 = 1.f;
    out[tid] = a0; out[tid+256] = a1;
}

// ------------------- exact kk-th smallest nonzero via 4-pass radix select ----
__global__ __launch_bounds__(1024) void kth_kernel(const float* __restrict__ ag) {
    __shared__ unsigned wh[32][256];
    __shared__ unsigned chist[256];
    __shared__ int s_k, s_rem; __shared__ unsigned s_pref;
    int b = blockIdx.x; int tid = threadIdx.x; int wid = tid >> 5;
    const float* f = ag + (long long)b*262144;
    for (int pass = 0; pass < 4; pass++) {
        int shift = 24 - 8*pass;
        for (int j = tid; j < 32*256; j += 1024) ((unsigned*)wh)[j] = 0u;
        __syncthreads();
        unsigned pref = (pass == 0) ? 0u : s_pref;
        int cb = -1; unsigned cc = 0;
        const float* p = f + tid*256;
        for (int j = 0; j < 256; j++) {
            unsigned ub = __float_as_uint(p[j]);
            int bin = -1;
            if (ub != 0u) {
                if (pass == 0 || (ub >> (shift+8)) == (pref >> (shift+8)))
                    bin = (int)((ub >> shift) & 255u);
            }
            if (bin == cb) cc++;
            else { if (cb >= 0) atomicAdd(&wh[wid][cb], cc); cb = bin; cc = 1u; }
        }
        if (cb >= 0) atomicAdd(&wh[wid][cb], cc);
        __syncthreads();
        if (tid < 256) {
            unsigned s = 0;
#pragma unroll
            for (int w = 0; w < 32; w++) s += wh[w][tid];
            chist[tid] = s;
        }
        __syncthreads();
        if (tid == 0) {
            if (pass == 0) {
                unsigned nnz = 0;
                for (int c = 0; c < 256; c++) nnz += chist[c];
                int kk = (int)floorf((float)((int)nnz - 512) * 0.3f);
                s_k = kk; s_rem = kk; s_pref = 0u;
            }
            if (s_k > 0) {
                int rem = s_rem; unsigned pf = s_pref;
                for (int c = 0; c < 256; c++) {
                    if ((int)chist[c] >= rem) { pf |= ((unsigned)c) << shift; break; }
                    rem -= (int)chist[c];
                }
                s_rem = rem; s_pref = pf;
            }
        }
        __syncthreads();
        if (s_k <= 0) break;
    }
    if (tid == 0) d_thre[b] = (s_k > 0) ? __uint_as_float(s_pref) : 0.f;
}

// ------------------- prune + ensemble + denom -------------------
__global__ void prune_kernel(const float* __restrict__ adj, float* __restrict__ ag) {
    int row = blockIdx.x; int b = row >> 9; int tid = threadIdx.x;
    float thre = d_thre[b];
    long long base = (long long)row*512;
    float s = 0.f;
#pragma unroll
    for (int u = 0; u < 2; u++) {
        int j = tid + u*256;
        float v = ag[base + j];
        v = (v <= thre) ? 0.f : v;
        ag[base + j] = v;
        float e = 0.5f*adj[base + j] + 0.5f*v;
        d_adjens[base + j] = e;
        s += e;
    }
    for (int o = 16; o; o >>= 1) s += __shfl_xor_sync(0xffffffffu, s, o);
    __shared__ float red[8];
    if ((tid & 31) == 0) red[tid >> 5] = s;
    __syncthreads();
    if (tid == 0) {
        float tot = 0.f;
#pragma unroll
        for (int w = 0; w < 8; w++) tot += red[w];
        d_denom[row] = tot + 1.f;
    }
}

// ------------------- host launcher -------------------
extern "C" void kernel_launch(void* const* d_in, const int* in_sizes, int n_in,
                              void* d_out, int out_size) {
    const float* adj    = (const float*)d_in[0];
    const int*   tok    = (const int*)d_in[1];
    const int*   pos    = (const int*)d_in[2];
    const int*   post   = (const int*)d_in[3];
    const int*   l      = (const int*)d_in[4];
    const float* emb    = (const float*)d_in[5];
    const float* pose   = (const float*)d_in[6];
    const float* poste  = (const float*)d_in[7];
    const float* Wih_f  = (const float*)d_in[8];
    const float* Whh_f  = (const float*)d_in[9];
    const float* bih_f  = (const float*)d_in[10];
    const float* bhh_f  = (const float*)d_in[11];
    const float* Wih_b  = (const float*)d_in[12];
    const float* Whh_b  = (const float*)d_in[13];
    const float* bih_b  = (const float*)d_in[14];
    const float* bhh_b  = (const float*)d_in[15];
    const float* Wq     = (const float*)d_in[16];
    const float* bq     = (const float*)d_in[17];
    const float* Wk     = (const float*)d_in[18];
    const float* bk     = (const float*)d_in[19];
    const float* W0     = (const float*)d_in[20];
    const float* b0     = (const float*)d_in[21];
    const float* W1     = (const float*)d_in[22];
    const float* b1     = (const float*)d_in[23];

    float* xo = (float*)d_out;                      // [B,S,256]
    float* ag = xo + 8388608;                       // [B,S,S]
    float* go = xo + 25165824;                      // [B,S,512]

    void *pv;
    cudaGetSymbolAddress(&pv, d_embs);   float* embs   = (float*)pv;
    cudaGetSymbolAddress(&pv, d_Xf);     float* Xf     = (float*)pv;
    cudaGetSymbolAddress(&pv, d_Xb);     float* Xb     = (float*)pv;
    cudaGetSymbolAddress(&pv, d_q);      float* qb     = (float*)pv;
    cudaGetSymbolAddress(&pv, d_k);      float* kb     = (float*)pv;
    cudaGetSymbolAddress(&pv, d_scores); float* sc     = (float*)pv;
    cudaGetSymbolAddress(&pv, d_adjens); float* ens    = (float*)pv;
    cudaGetSymbolAddress(&pv, d_tb);     float* tbuf   = (float*)pv;
    cudaGetSymbolAddress(&pv, d_x1);     float* x1     = (float*)pv;
    cudaGetSymbolAddress(&pv, d_denom);  float* den    = (float*)pv;
    cudaGetSymbolAddress(&pv, d_biasf);  float* biasf  = (float*)pv;
    cudaGetSymbolAddress(&pv, d_biasb);  float* biasb  = (float*)pv;

    cudaMemsetAsync(go, 0, (size_t)NROWS*512*sizeof(float));
    prep_kernel<<<4,256>>>(bih_f, bhh_f, bih_b, bhh_b);
    init_kernel<<<16,1024>>>();
    embed_kernel<<<32768,128>>>(tok, pos, post, emb, pose, poste);

    // X = embs @ Wih^T + bias   [32768,1024]  (skip row tiles beyond l[b])
    sgemm_nt<<<dim3(8,256,1),256>>>(embs,360,0,0, Wih_f,360,0,0, Xf,1024,0,0,
                                    1,360,1.f, biasf, nullptr, 0, l, 0);
    sgemm_nt<<<dim3(8,256,1),256>>>(embs,360,0,0, Wih_b,360,0,0, Xb,1024,0,0,
                                    1,360,1.f, biasb, nullptr, 0, l, 0);

    cudaFuncSetAttribute(lstm_kernel, cudaFuncAttributeMaxDynamicSharedMemorySize, 36096*4);
    lstm_kernel<<<128,512,36096*4>>>(Whh_f, Whh_b, l, go);

    // q, k (skip row tiles beyond l[b])
    sgemm_nt<<<dim3(4,256,1),256>>>(go,512,0,0, Wq,512,0,0, qb,512,0,0,
                                    1,512,1.f, bq, nullptr, 0, l, 0);
    sgemm_nt<<<dim3(4,256,1),256>>>(go,512,0,0, Wk,512,0,0, kb,512,0,0,
                                    1,512,1.f, bk, nullptr, 0, l, 0);
    // scores[b,h] = q_bh @ k_bh^T / sqrt(128)  (skip row AND col tiles >= l[b])
    float alpha = 1.f/sqrtf(128.f);
    sgemm_nt<<<dim3(4,4,256),256>>>(qb,512, 262144,128, kb,512, 262144,128,
                                    sc,512, 1048576,262144, 4,128, alpha,
                                    nullptr, nullptr, 0, l, 1);
    softmax_kernel<<<32768,256>>>(l, ag);
    kth_kernel<<<64,1024>>>(ag);
    prune_kernel<<<32768,256>>>(adj, ag);

    // GCN layer 1: t = adjens @ g ; x1 = relu((t@W0^T+b0)/denom)
    sgemm_nn<<<dim3(4,4,64),256>>>(ens,512,262144, go,512,262144, tbuf,512,262144, 512);
    sgemm_nt<<<dim3(2,256,1),256>>>(tbuf,512,0,0, W0,512,0,0, x1,256,0,0,
                                    1,512,1.f, b0, den, 1, nullptr, 0);
    // GCN layer 2: t2 = adjens @ x1 ; x = relu((t2@W1^T+b1)/denom)
    sgemm_nn<<<dim3(2,4,64),256>>>(ens,512,262144, x1,256,131072, tbuf,256,131072, 512);
    sgemm_nt<<<dim3(2,256,1),256>>>(tbuf,256,0,0, W1,256,0,0, xo,256,0,0,
                                    1,256,1.f, b1, den, 1, nullptr, 0);
    (void)in_sizes; (void)n_in; (void)out_size;
}

// round 5
// speedup vs baseline: 1.1047x; 1.0434x over previous
#include <cuda_runtime.h>
#include <math.h>

#define SS 512
#define NROWS 32768LL

// ------------------- device scratch (no allocs allowed) -------------------
__device__ float d_embs[32768*360];
__device__ float d_Xf[32768*1024];
__device__ float d_Xb[32768*1024];
__device__ float d_q[32768*512];
__device__ float d_k[32768*512];
__device__ float d_scores[67108864];
__device__ float d_adjens[16777216];
__device__ float d_tb[16777216];
__device__ float d_x1[8388608];
__device__ float d_denom[32768];
__device__ float d_thre[64];
__device__ float d_biasf[1024];
__device__ float d_biasb[1024];
__device__ float4 d_hx4[2*16*512];
__device__ unsigned d_barc[16];

// ------------------- small prep kernels -------------------
__global__ void prep_kernel(const float* bihf, const float* bhhf,
                            const float* bihb, const float* bhhb) {
    int i = blockIdx.x*blockDim.x + threadIdx.x;
    if (i < 1024) { d_biasf[i] = bihf[i]+bhhf[i]; d_biasb[i] = bihb[i]+bhhb[i]; }
}

__global__ void init_kernel() {
    int i = blockIdx.x*blockDim.x + threadIdx.x;
    if (i < 16) d_barc[i] = 0u;
    float4 z = make_float4(0.f,0.f,0.f,0.f);
    for (int j = i; j < 2*16*512; j += blockDim.x*gridDim.x) d_hx4[j] = z;
}

__global__ void embed_kernel(const int* __restrict__ tok, const int* __restrict__ pos,
                             const int* __restrict__ post, const float* __restrict__ emb,
                             const float* __restrict__ pose, const float* __restrict__ poste) {
    int r = blockIdx.x;
    int t = tok[r], p = pos[r], q = post[r];
    float* o = d_embs + (long long)r*360;
    for (int d = threadIdx.x; d < 360; d += blockDim.x) {
        float v;
        if (d < 300)      v = emb[(long long)t*300 + d];
        else if (d < 330) v = pose[p*30 + (d-300)];
        else              v = poste[q*30 + (d-330)];
        o[d] = v;
    }
}

#define COMPUTE_TILE(buf)                                               \
    _Pragma("unroll")                                                   \
    for (int kk = 0; kk < 8; kk++) {                                    \
        float av[8], bv[8];                                             \
        *(float4*)&av[0] = *(const float4*)&As[buf][kk][ty];            \
        *(float4*)&av[4] = *(const float4*)&As[buf][kk][ty+4];          \
        *(float4*)&bv[0] = *(const float4*)&Bs[buf][kk][tx];            \
        *(float4*)&bv[4] = *(const float4*)&Bs[buf][kk][tx+4];          \
        _Pragma("unroll")                                               \
        for (int i = 0; i < 8; i++)                                     \
            _Pragma("unroll")                                           \
            for (int j = 0; j < 8; j++)                                 \
                acc[i][j] = fmaf(av[i], bv[j], acc[i][j]);              \
    }

// ------------------- SGEMM NT (3-stage pipeline, conflict-free stores):
// C = alpha*A[M,K]@B[N,K]^T (+bias)(/denom)(relu), with optional length-skip.
__global__ __launch_bounds__(256,2) void sgemm_nt(
    const float* __restrict__ A, int lda, long long sAo, long long sAi,
    const float* __restrict__ B, int ldb, long long sBo, long long sBi,
    float* __restrict__ C, int ldc, long long sCo, long long sCi,
    int innerZ, int K, float alpha,
    const float* __restrict__ bias, const float* __restrict__ denom, int relu,
    const int* __restrict__ lens, int colskip)
{
    int z = blockIdx.z; int zo = z / innerZ; int zi = z - zo*innerZ;
    if (lens) {
        int rowg = blockIdx.y*128;
        int bsm = (innerZ > 1) ? zo : (rowg >> 9);
        int lb = lens[bsm];
        int rloc = (innerZ > 1) ? rowg : (rowg & 511);
        if (rloc >= lb) return;
        if (colskip && blockIdx.x*128 >= lb) return;
    }
    A += zo*sAo + zi*sAi; B += zo*sBo + zi*sBi; C += zo*sCo + zi*sCi;
    __shared__ float As[3][8][128];
    __shared__ float Bs[3][8][128];
    int tid = threadIdx.x;
    int r = tid & 127;
    const float* G = (tid < 128)
        ? (A + (long long)(blockIdx.y*128 + r)*lda)
        : (B + (long long)(blockIdx.x*128 + r)*ldb);
    float (*S)[8][128] = (tid < 128) ? As : Bs;

    float acc[8][8];
#pragma unroll
    for (int i = 0; i < 8; i++)
#pragma unroll
        for (int j = 0; j < 8; j++) acc[i][j] = 0.f;
    int tx = (tid & 15) * 8;
    int ty = (tid >> 4) * 8;

    int KT = K >> 3;
    {
        float4 p0 = *(const float4*)(G + 0);
        float4 p1 = *(const float4*)(G + 4);
        S[0][0][r]=p0.x; S[0][1][r]=p0.y; S[0][2][r]=p0.z; S[0][3][r]=p0.w;
        S[0][4][r]=p1.x; S[0][5][r]=p1.y; S[0][6][r]=p1.z; S[0][7][r]=p1.w;
        p0 = *(const float4*)(G + 8);
        p1 = *(const float4*)(G + 12);
        S[1][0][r]=p0.x; S[1][1][r]=p0.y; S[1][2][r]=p0.z; S[1][3][r]=p0.w;
        S[1][4][r]=p1.x; S[1][5][r]=p1.y; S[1][6][r]=p1.z; S[1][7][r]=p1.w;
    }
    __syncthreads();
    int cur = 0;
    for (int kt = 2; kt < KT; kt++) {
        int k0 = kt << 3;
        float4 p0 = *(const float4*)(G + k0);
        float4 p1 = *(const float4*)(G + k0 + 4);
        COMPUTE_TILE(cur);
        int st = kt % 3;
        S[st][0][r]=p0.x; S[st][1][r]=p0.y; S[st][2][r]=p0.z; S[st][3][r]=p0.w;
        S[st][4][r]=p1.x; S[st][5][r]=p1.y; S[st][6][r]=p1.z; S[st][7][r]=p1.w;
        __syncthreads();
        cur++; if (cur == 3) cur = 0;
    }
    COMPUTE_TILE(cur);
    cur++; if (cur == 3) cur = 0;
    COMPUTE_TILE(cur);

    int rowBase = blockIdx.y*128 + ty;
    int colBase = blockIdx.x*128 + tx;
#pragma unroll
    for (int i = 0; i < 8; i++) {
        int row = rowBase + i;
        float rd = denom ? (1.0f/denom[row]) : 1.0f;
        float* crow = C + (long long)row*ldc + colBase;
#pragma unroll
        for (int j = 0; j < 8; j++) {
            float v = acc[i][j] * alpha;
            if (bias) v += bias[colBase + j];
            v *= rd;
            if (relu) v = fmaxf(v, 0.f);
            crow[j] = v;
        }
    }
}

// ------------------- SGEMM NN (batched, 3-stage): C = A[M,K]@B[K,N]
// lens: per-z sample length; skip row tiles >= l (C pre-zeroed) and clamp K.
__global__ __launch_bounds__(256,2) void sgemm_nn(
    const float* __restrict__ A, int lda, long long sA,
    const float* __restrict__ B, int ldb, long long sB,
    float* __restrict__ C, int ldc, long long sC, int K,
    const int* __restrict__ lens)
{
    int z = blockIdx.z;
    if (lens) {
        int lb = lens[z];
        if (blockIdx.y*128 >= lb) return;
        int Keff = ((lb + 7) >> 3) << 3;
        if (Keff < K) K = Keff;
    }
    A += (long long)z*sA; B += (long long)z*sB; C += (long long)z*sC;
    __shared__ float As[3][8][128];
    __shared__ float Bs[3][8][128];
    int tid = threadIdx.x;
    int r = tid & 127;

    const float* G;
    int kRow = 0, cB = 0;
    if (tid < 128) {
        G = A + (long long)(blockIdx.y*128 + r)*lda;
    } else {
        kRow = r >> 4; cB = (r & 15) * 8;
        G = B + (long long)kRow*ldb + blockIdx.x*128 + cB;
    }

    float acc[8][8];
#pragma unroll
    for (int i = 0; i < 8; i++)
#pragma unroll
        for (int j = 0; j < 8; j++) acc[i][j] = 0.f;
    int tx = (tid & 15) * 8;
    int ty = (tid >> 4) * 8;

    int KT = K >> 3;
    if (tid < 128) {
        float4 p0 = *(const float4*)(G + 0);
        float4 p1 = *(const float4*)(G + 4);
        As[0][0][r]=p0.x; As[0][1][r]=p0.y; As[0][2][r]=p0.z; As[0][3][r]=p0.w;
        As[0][4][r]=p1.x; As[0][5][r]=p1.y; As[0][6][r]=p1.z; As[0][7][r]=p1.w;
        p0 = *(const float4*)(G + 8);
        p1 = *(const float4*)(G + 12);
        As[1][0][r]=p0.x; As[1][1][r]=p0.y; As[1][2][r]=p0.z; As[1][3][r]=p0.w;
        As[1][4][r]=p1.x; As[1][5][r]=p1.y; As[1][6][r]=p1.z; As[1][7][r]=p1.w;
    } else {
        float4 p0 = *(const float4*)(G);
        float4 p1 = *(const float4*)(G + 4);
        *(float4*)&Bs[0][kRow][cB]   = p0;
        *(float4*)&Bs[0][kRow][cB+4] = p1;
        p0 = *(const float4*)(G + (long long)8*ldb);
        p1 = *(const float4*)(G + (long long)8*ldb + 4);
        *(float4*)&Bs[1][kRow][cB]   = p0;
        *(float4*)&Bs[1][kRow][cB+4] = p1;
    }
    __syncthreads();
    int cur = 0;
    for (int kt = 2; kt < KT; kt++) {
        int k0 = kt << 3;
        float4 p0, p1;
        if (tid < 128) {
            p0 = *(const float4*)(G + k0);
            p1 = *(const float4*)(G + k0 + 4);
        } else {
            p0 = *(const float4*)(G + (long long)k0*ldb);
            p1 = *(const float4*)(G + (long long)k0*ldb + 4);
        }
        COMPUTE_TILE(cur);
        int st = kt % 3;
        if (tid < 128) {
            As[st][0][r]=p0.x; As[st][1][r]=p0.y; As[st][2][r]=p0.z; As[st][3][r]=p0.w;
            As[st][4][r]=p1.x; As[st][5][r]=p1.y; As[st][6][r]=p1.z; As[st][7][r]=p1.w;
        } else {
            *(float4*)&Bs[st][kRow][cB]   = p0;
            *(float4*)&Bs[st][kRow][cB+4] = p1;
        }
        __syncthreads();
        cur++; if (cur == 3) cur = 0;
    }
    COMPUTE_TILE(cur);
    cur++; if (cur == 3) cur = 0;
    COMPUTE_TILE(cur);

    int rowBase = blockIdx.y*128 + ty;
    int colBase = blockIdx.x*128 + tx;
#pragma unroll
    for (int i = 0; i < 8; i++) {
        float* crow = C + (long long)(rowBase+i)*ldc + colBase;
#pragma unroll
        for (int j = 0; j < 8; j++) crow[j] = acc[i][j];
    }
}

// ------------------- BiLSTM recurrence (unchanged, passing) -----------
__global__ __launch_bounds__(512) void lstm_kernel(
    const float* __restrict__ Whhf, const float* __restrict__ Whhb,
    const int* __restrict__ l, float* __restrict__ gout)
{
    extern __shared__ float sm[];
    float* Ws = sm;
    float* hs = sm + 32768;
    float* gs = hs + 2048;
    float* cs = gs + 1024;
    int bid = blockIdx.x; int group = bid >> 3; int q = bid & 7;
    int dir = group >> 3; int sg = group & 7;
    int tid = threadIdx.x;
    const float* Whh = dir ? Whhb : Whhf;
    const float* Xd = dir ? d_Xb : d_Xf;
    for (int idx = tid; idx < 32768; idx += 512) {
        int rr = idx >> 8; int kk = idx & 255;
        int gr = ((rr>>5)<<8) + (q<<5) + (rr&31);
        Ws[(((kk>>2)*128)+rr)*4 + (kk&3)] = Whh[gr*256 + kk];
    }
    if (tid < 256) cs[tid] = 0.f;
    int ln[8]; int lmax = 0;
#pragma unroll
    for (int n = 0; n < 8; n++) { ln[n] = l[sg*8+n]; lmax = max(lmax, ln[n]); }
    int slot = tid >> 7; int r = tid & 127;
    int n0 = slot, n1 = slot + 4;
    int b0 = sg*8+n0, b1 = sg*8+n1;
    int grow = ((r>>5)<<8) + (q<<5) + (r&31);
    __syncthreads();
    const float4* Ws4 = (const float4*)Ws;
    for (int t = 0; t < lmax; t++) {
        ((float4*)hs)[tid] = __ldcg(&d_hx4[(t&1)*8192 + group*512 + tid]);
        __syncthreads();
        int t0 = dir ? (ln[n0]-1-t) : t;
        int t1 = dir ? (ln[n1]-1-t) : t;
        float acc0 = (t < ln[n0]) ? Xd[((long long)(b0*SS+t0)<<10) + grow] : 0.f;
        float acc1 = (t < ln[n1]) ? Xd[((long long)(b1*SS+t1)<<10) + grow] : 0.f;
        const float4* ha = (const float4*)(hs + n0*256);
        const float4* hb = (const float4*)(hs + n1*256);
#pragma unroll 8
        for (int k4 = 0; k4 < 64; k4++) {
            float4 w = Ws4[k4*128 + r];
            float4 x = ha[k4], y = hb[k4];
            acc0 = fmaf(w.x,x.x, fmaf(w.y,x.y, fmaf(w.z,x.z, fmaf(w.w,x.w, acc0))));
            acc1 = fmaf(w.x,y.x, fmaf(w.y,y.y, fmaf(w.z,y.z, fmaf(w.w,y.w, acc1))));
        }
        gs[n0*128 + r] = acc0; gs[n1*128 + r] = acc1;
        __syncthreads();
        if (tid < 256) {
            int n = tid >> 5, jl = tid & 31;
            if (t < ln[n]) {
                float gi = gs[n*128+jl], gf = gs[n*128+32+jl];
                float gg = gs[n*128+64+jl], go_ = gs[n*128+96+jl];
                float c = cs[n*32+jl];
                c = (1.f/(1.f+expf(-gf)))*c + (1.f/(1.f+expf(-gi)))*tanhf(gg);
                float h = (1.f/(1.f+expf(-go_)))*tanhf(c);
                cs[n*32+jl] = c;
                float* dst = (float*)&d_hx4[((t+1)&1)*8192 + group*512];
                __stcg(dst + n*256 + q*32 + jl, h);
                int bsm = sg*8+n;
                int tpos = dir ? (ln[n]-1-t) : t;
                gout[((long long)(bsm*SS+tpos))*512 + dir*256 + q*32 + jl] = h;
            }
        }
        __threadfence();
        __syncthreads();
        if (tid == 0) {
            atomicAdd(&d_barc[group], 1u);
            unsigned tgt = (unsigned)(t+1)*8u;
            while (atomicAdd(&d_barc[group], 0u) < tgt) { }
        }
        __syncthreads();
    }
}

// ------------------- masked softmax + head mean + diag -------------------
__global__ void softmax_kernel(const int* __restrict__ l, float* __restrict__ ag) {
    int row = blockIdx.x; int b = row >> 9; int i = row & 511;
    int lb = l[b];
    float* out = ag + (long long)row*512;
    int tid = threadIdx.x;
    if (i >= lb) { out[tid] = 0.f; out[tid+256] = 0.f; return; }
    __shared__ float red[8];
    float a0 = 0.f, a1 = 0.f;
    int lane = tid & 31, wid = tid >> 5;
    for (int h = 0; h < 4; h++) {
        const float* sr = d_scores + ((long long)((b*4+h)*512 + i))*512;
        float v0 = (tid < lb)     ? sr[tid]     : -3.0e38f;
        float v1 = (tid+256 < lb) ? sr[tid+256] : -3.0e38f;
        float m = fmaxf(v0, v1);
        for (int o = 16; o; o >>= 1) m = fmaxf(m, __shfl_xor_sync(0xffffffffu, m, o));
        if (lane == 0) red[wid] = m;
        __syncthreads();
        m = red[0];
#pragma unroll
        for (int w = 1; w < 8; w++) m = fmaxf(m, red[w]);
        __syncthreads();
        float e0 = (tid < lb)     ? expf(v0 - m) : 0.f;
        float e1 = (tid+256 < lb) ? expf(v1 - m) : 0.f;
        float s = e0 + e1;
        for (int o = 16; o; o >>= 1) s += __shfl_xor_sync(0xffffffffu, s, o);
        if (lane == 0) red[wid] = s;
        __syncthreads();
        s = 0.f;
#pragma unroll
        for (int w = 0; w < 8; w++) s += red[w];
        float inv = 1.f/s;
        a0 += e0*inv; a1 += e1*inv;
        __syncthreads();
    }
    a0 *= 0.25f; a1 *= 0.25f;
    if (tid == i) a0 = 1.f;
    if (tid+256 == i) a1 = 1.f;
    out[tid] = a0; out[tid+256] = a1;
}

// ------------- exact kk-th smallest nonzero via 4-pass radix select ----------
// coalesced reads + per-warp smem histograms
__global__ __launch_bounds__(1024) void kth_kernel(const float* __restrict__ ag) {
    __shared__ unsigned wh[32][256];
    __shared__ unsigned chist[256];
    __shared__ int s_k, s_rem; __shared__ unsigned s_pref;
    int b = blockIdx.x; int tid = threadIdx.x; int wid = tid >> 5;
    const float* f = ag + (long long)b*262144;
    for (int pass = 0; pass < 4; pass++) {
        int shift = 24 - 8*pass;
        for (int j = tid; j < 32*256; j += 1024) ((unsigned*)wh)[j] = 0u;
        __syncthreads();
        unsigned pref = (pass == 0) ? 0u : s_pref;
        unsigned prefHi = pref >> (shift+8);
        for (int j = tid; j < 262144; j += 1024) {
            unsigned ub = __float_as_uint(f[j]);
            if (ub != 0u) {
                if (pass == 0 || (ub >> (shift+8)) == prefHi)
                    atomicAdd(&wh[wid][(ub >> shift) & 255u], 1u);
            }
        }
        __syncthreads();
        if (tid < 256) {
            unsigned s = 0;
#pragma unroll
            for (int w = 0; w < 32; w++) s += wh[w][tid];
            chist[tid] = s;
        }
        __syncthreads();
        if (tid == 0) {
            if (pass == 0) {
                unsigned nnz = 0;
                for (int c = 0; c < 256; c++) nnz += chist[c];
                int kk = (int)floorf((float)((int)nnz - 512) * 0.3f);
                s_k = kk; s_rem = kk; s_pref = 0u;
            }
            if (s_k > 0) {
                int rem = s_rem; unsigned pf = s_pref;
                for (int c = 0; c < 256; c++) {
                    if ((int)chist[c] >= rem) { pf |= ((unsigned)c) << shift; break; }
                    rem -= (int)chist[c];
                }
                s_rem = rem; s_pref = pf;
            }
        }
        __syncthreads();
        if (s_k <= 0) break;
    }
    if (tid == 0) d_thre[b] = (s_k > 0) ? __uint_as_float(s_pref) : 0.f;
}

// ------------------- prune + ensemble + denom -------------------
__global__ void prune_kernel(const float* __restrict__ adj, float* __restrict__ ag) {
    int row = blockIdx.x; int b = row >> 9; int tid = threadIdx.x;
    float thre = d_thre[b];
    long long base = (long long)row*512;
    float s = 0.f;
#pragma unroll
    for (int u = 0; u < 2; u++) {
        int j = tid + u*256;
        float v = ag[base + j];
        v = (v <= thre) ? 0.f : v;
        ag[base + j] = v;
        float e = 0.5f*adj[base + j] + 0.5f*v;
        d_adjens[base + j] = e;
        s += e;
    }
    for (int o = 16; o; o >>= 1) s += __shfl_xor_sync(0xffffffffu, s, o);
    __shared__ float red[8];
    if ((tid & 31) == 0) red[tid >> 5] = s;
    __syncthreads();
    if (tid == 0) {
        float tot = 0.f;
#pragma unroll
        for (int w = 0; w < 8; w++) tot += red[w];
        d_denom[row] = tot + 1.f;
    }
}

// ------------------- host launcher -------------------
extern "C" void kernel_launch(void* const* d_in, const int* in_sizes, int n_in,
                              void* d_out, int out_size) {
    const float* adj    = (const float*)d_in[0];
    const int*   tok    = (const int*)d_in[1];
    const int*   pos    = (const int*)d_in[2];
    const int*   post   = (const int*)d_in[3];
    const int*   l      = (const int*)d_in[4];
    const float* emb    = (const float*)d_in[5];
    const float* pose   = (const float*)d_in[6];
    const float* poste  = (const float*)d_in[7];
    const float* Wih_f  = (const float*)d_in[8];
    const float* Whh_f  = (const float*)d_in[9];
    const float* bih_f  = (const float*)d_in[10];
    const float* bhh_f  = (const float*)d_in[11];
    const float* Wih_b  = (const float*)d_in[12];
    const float* Whh_b  = (const float*)d_in[13];
    const float* bih_b  = (const float*)d_in[14];
    const float* bhh_b  = (const float*)d_in[15];
    const float* Wq     = (const float*)d_in[16];
    const float* bq     = (const float*)d_in[17];
    const float* Wk     = (const float*)d_in[18];
    const float* bk     = (const float*)d_in[19];
    const float* W0     = (const float*)d_in[20];
    const float* b0     = (const float*)d_in[21];
    const float* W1     = (const float*)d_in[22];
    const float* b1     = (const float*)d_in[23];

    float* xo = (float*)d_out;                      // [B,S,256]
    float* ag = xo + 8388608;                       // [B,S,S]
    float* go = xo + 25165824;                      // [B,S,512]

    void *pv;
    cudaGetSymbolAddress(&pv, d_embs);   float* embs   = (float*)pv;
    cudaGetSymbolAddress(&pv, d_Xf);     float* Xf     = (float*)pv;
    cudaGetSymbolAddress(&pv, d_Xb);     float* Xb     = (float*)pv;
    cudaGetSymbolAddress(&pv, d_q);      float* qb     = (float*)pv;
    cudaGetSymbolAddress(&pv, d_k);      float* kb     = (float*)pv;
    cudaGetSymbolAddress(&pv, d_scores); float* sc     = (float*)pv;
    cudaGetSymbolAddress(&pv, d_adjens); float* ens    = (float*)pv;
    cudaGetSymbolAddress(&pv, d_tb);     float* tbuf   = (float*)pv;
    cudaGetSymbolAddress(&pv, d_x1);     float* x1     = (float*)pv;
    cudaGetSymbolAddress(&pv, d_denom);  float* den    = (float*)pv;
    cudaGetSymbolAddress(&pv, d_biasf);  float* biasf  = (float*)pv;
    cudaGetSymbolAddress(&pv, d_biasb);  float* biasb  = (float*)pv;

    cudaMemsetAsync(go, 0, (size_t)NROWS*512*sizeof(float));
    prep_kernel<<<4,256>>>(bih_f, bhh_f, bih_b, bhh_b);
    init_kernel<<<16,1024>>>();
    embed_kernel<<<32768,128>>>(tok, pos, post, emb, pose, poste);

    // X = embs @ Wih^T + bias   [32768,1024]  (skip row tiles beyond l[b])
    sgemm_nt<<<dim3(8,256,1),256>>>(embs,360,0,0, Wih_f,360,0,0, Xf,1024,0,0,
                                    1,360,1.f, biasf, nullptr, 0, l, 0);
    sgemm_nt<<<dim3(8,256,1),256>>>(embs,360,0,0, Wih_b,360,0,0, Xb,1024,0,0,
                                    1,360,1.f, biasb, nullptr, 0, l, 0);

    cudaFuncSetAttribute(lstm_kernel, cudaFuncAttributeMaxDynamicSharedMemorySize, 36096*4);
    lstm_kernel<<<128,512,36096*4>>>(Whh_f, Whh_b, l, go);

    // q, k (skip row tiles beyond l[b])
    sgemm_nt<<<dim3(4,256,1),256>>>(go,512,0,0, Wq,512,0,0, qb,512,0,0,
                                    1,512,1.f, bq, nullptr, 0, l, 0);
    sgemm_nt<<<dim3(4,256,1),256>>>(go,512,0,0, Wk,512,0,0, kb,512,0,0,
                                    1,512,1.f, bk, nullptr, 0, l, 0);
    // scores[b,h] = q_bh @ k_bh^T / sqrt(128)  (skip row AND col tiles >= l[b])
    float alpha = 1.f/sqrtf(128.f);
    sgemm_nt<<<dim3(4,4,256),256>>>(qb,512, 262144,128, kb,512, 262144,128,
                                    sc,512, 1048576,262144, 4,128, alpha,
                                    nullptr, nullptr, 0, l, 1);
    softmax_kernel<<<32768,256>>>(l, ag);
    kth_kernel<<<64,1024>>>(ag);
    prune_kernel<<<32768,256>>>(adj, ag);

    // GCN layer 1: t = adjens @ g ; x1 = relu((t@W0^T+b0)/denom)
    cudaMemsetAsync(tbuf, 0, (size_t)16777216*sizeof(float));
    sgemm_nn<<<dim3(4,4,64),256>>>(ens,512,262144, go,512,262144, tbuf,512,262144, 512, l);
    sgemm_nt<<<dim3(2,256,1),256>>>(tbuf,512,0,0, W0,512,0,0, x1,256,0,0,
                                    1,512,1.f, b0, den, 1, nullptr, 0);
    // GCN layer 2: t2 = adjens @ x1 ; x = relu((t2@W1^T+b1)/denom)
    cudaMemsetAsync(tbuf, 0, (size_t)8388608*sizeof(float));
    sgemm_nn<<<dim3(2,4,64),256>>>(ens,512,262144, x1,256,131072, tbuf,256,131072, 512, l);
    sgemm_nt<<<dim3(2,256,1),256>>>(tbuf,256,0,0, W1,256,0,0, xo,256,0,0,
                                    1,256,1.f, b1, den, 1, nullptr, 0);
    (void)in_sizes; (void)n_in; (void)out_size;
}